// round 1
// baseline (speedup 1.0000x reference)
#include <cuda_runtime.h>
#include <math.h>

#define N_NODES 50000
#define N_EDGES 800000
#define D 64
#define C 8

// Scratch (device globals — no allocations allowed).
__device__ float g_Y[(size_t)N_NODES * 25 * D];   // max K^E = 25 (layer 2)
__device__ float g_h[(size_t)N_NODES * D];        // features between layers
__device__ float g_msum[(size_t)N_NODES * D];     // segment sum accumulator
__device__ float g_cnt[N_NODES];                  // segment counts

// ---------------------------------------------------------------------------
// Zero the accumulators
// ---------------------------------------------------------------------------
__global__ void zero_accum_kernel() {
    int i = blockIdx.x * blockDim.x + threadIdx.x;
    if (i < N_NODES * D) g_msum[i] = 0.0f;
    if (i < N_NODES)     g_cnt[i]  = 0.0f;
}

// ---------------------------------------------------------------------------
// Y[n,k,o] = sum_d in[n,d] * W[k,d,o]
// One thread per output element. Warp covers consecutive o of same (n,k):
// in[n,d] is a broadcast load, W[k,d,o] is a coalesced 128B load per d.
// ---------------------------------------------------------------------------
template<bool FROM_H>
__global__ void compute_Y_kernel(const float* __restrict__ xin,
                                 const float* __restrict__ W, int KE) {
    long long tid = (long long)blockIdx.x * blockDim.x + threadIdx.x;
    long long total = (long long)N_NODES * KE * D;
    if (tid >= total) return;
    int o = (int)(tid & (D - 1));
    long long r = tid >> 6;
    int k = (int)(r % KE);
    int n = (int)(r / KE);

    const float* __restrict__ x = FROM_H ? g_h : xin;
    const float* xr = x + (long long)n * D;
    const float* wc = W + (long long)k * D * D + o;
    float acc = 0.0f;
#pragma unroll
    for (int d = 0; d < D; d++) {
        acc = fmaf(xr[d], wc[(long long)d * D], acc);
    }
    g_Y[((long long)n * KE + k) * D + o] = acc;
}

// ---------------------------------------------------------------------------
// Edge pass: for each edge, compute degree-1 open B-spline basis over 2 dims,
// gather 4 rows of Y[src], blend, atomically accumulate into msum[dst].
// 16 threads per edge; each handles a float4 (4 output dims).
// ---------------------------------------------------------------------------
template<int K>
__global__ void edge_pass_kernel(const int* __restrict__ ei,
                                 const float* __restrict__ ea) {
    const int KE = K * K;
    long long gid = (long long)blockIdx.x * blockDim.x + threadIdx.x;
    int e = (int)(gid >> 4);
    int lane = (int)(gid & 15);
    if (e >= N_EDGES) return;

    int src = ei[e];
    int dst = ei[N_EDGES + e];

    float p0 = ea[2 * e + 0];
    float p1 = ea[2 * e + 1];

    // dim 0
    float v0 = p0 * (float)(K - 1);
    float lo0 = floorf(v0);
    float f0 = v0 - lo0;
    int l0 = (int)lo0;
    int i00 = min(max(l0, 0), K - 1);
    int i01 = min(max(l0 + 1, 0), K - 1);
    // dim 1
    float v1 = p1 * (float)(K - 1);
    float lo1 = floorf(v1);
    float f1 = v1 - lo1;
    int l1 = (int)lo1;
    int i10 = min(max(l1, 0), K - 1);
    int i11 = min(max(l1 + 1, 0), K - 1);

    float b00 = 1.0f - f0, b01 = f0;
    float b10 = 1.0f - f1, b11 = f1;

    // combos in 'ij' meshgrid order: (0,0),(0,1),(1,0),(1,1)
    // stride: dim0 -> 1, dim1 -> K
    int   wi[4];
    float B[4];
    wi[0] = i00 + i10 * K;  B[0] = b00 * b10;
    wi[1] = i00 + i11 * K;  B[1] = b00 * b11;
    wi[2] = i01 + i10 * K;  B[2] = b01 * b10;
    wi[3] = i01 + i11 * K;  B[3] = b01 * b11;

    long long base = (long long)src * KE * D;
    float4 acc = make_float4(0.f, 0.f, 0.f, 0.f);
#pragma unroll
    for (int s = 0; s < 4; s++) {
        const float4* row = reinterpret_cast<const float4*>(g_Y + base + (long long)wi[s] * D);
        float4 y = row[lane];
        acc.x = fmaf(B[s], y.x, acc.x);
        acc.y = fmaf(B[s], y.y, acc.y);
        acc.z = fmaf(B[s], y.z, acc.z);
        acc.w = fmaf(B[s], y.w, acc.w);
    }

    float* mrow = g_msum + (long long)dst * D + lane * 4;
    atomicAdd(mrow + 0, acc.x);
    atomicAdd(mrow + 1, acc.y);
    atomicAdd(mrow + 2, acc.z);
    atomicAdd(mrow + 3, acc.w);
    if (lane == 0) atomicAdd(&g_cnt[dst], 1.0f);
}

// ---------------------------------------------------------------------------
// Node pass: hout[n,:] = elu( msum[n,:]/max(cnt,1) + hin[n,:] @ root + bias )
// One warp per node; lane handles outputs o and o+32.
// ---------------------------------------------------------------------------
template<bool IN_FROM_H>
__global__ void node_pass_kernel(const float* __restrict__ hin_g,
                                 const float* __restrict__ root,
                                 const float* __restrict__ bias) {
    int n = blockIdx.x * (blockDim.x >> 5) + (threadIdx.x >> 5);
    int lane = threadIdx.x & 31;
    if (n >= N_NODES) return;

    const float* __restrict__ hin = IN_FROM_H ? g_h : hin_g;
    const float* hr = hin + (long long)n * D;

    float a0 = 0.0f, a1 = 0.0f;
#pragma unroll
    for (int d = 0; d < D; d++) {
        float hv = hr[d];  // warp broadcast
        a0 = fmaf(hv, root[d * D + lane], a0);
        a1 = fmaf(hv, root[d * D + lane + 32], a1);
    }
    float c = fmaxf(g_cnt[n], 1.0f);
    float invc = 1.0f / c;
    float m0 = g_msum[(long long)n * D + lane] * invc + a0 + bias[lane];
    float m1 = g_msum[(long long)n * D + lane + 32] * invc + a1 + bias[lane + 32];

    // ELU (alpha = 1)
    m0 = (m0 > 0.0f) ? m0 : expm1f(m0);
    m1 = (m1 > 0.0f) ? m1 : expm1f(m1);

    g_h[(long long)n * D + lane]      = m0;
    g_h[(long long)n * D + lane + 32] = m1;
}

// ---------------------------------------------------------------------------
// MLP tail: out = relu( relu(h @ w1 + b1) @ w2 + b2 ).  One warp per node.
// ---------------------------------------------------------------------------
__global__ void mlp_kernel(const float* __restrict__ w1, const float* __restrict__ b1,
                           const float* __restrict__ w2, const float* __restrict__ b2,
                           float* __restrict__ out) {
    __shared__ float t1s[8][D];
    int wid = threadIdx.x >> 5;
    int lane = threadIdx.x & 31;
    int n = blockIdx.x * 8 + wid;
    if (n >= N_NODES) return;

    const float* hr = g_h + (long long)n * D;
    float a0 = 0.0f, a1 = 0.0f;
#pragma unroll
    for (int d = 0; d < D; d++) {
        float hv = hr[d];
        a0 = fmaf(hv, w1[d * D + lane], a0);
        a1 = fmaf(hv, w1[d * D + lane + 32], a1);
    }
    a0 += b1[lane];
    a1 += b1[lane + 32];
    t1s[wid][lane]      = fmaxf(a0, 0.0f);
    t1s[wid][lane + 32] = fmaxf(a1, 0.0f);
    __syncwarp();

    if (lane < C) {
        float acc = b2[lane];
#pragma unroll
        for (int d = 0; d < D; d++) {
            acc = fmaf(t1s[wid][d], w2[d * C + lane], acc);
        }
        out[(long long)n * C + lane] = fmaxf(acc, 0.0f);
    }
}

// ---------------------------------------------------------------------------
// Launch
// ---------------------------------------------------------------------------
extern "C" void kernel_launch(void* const* d_in, const int* in_sizes, int n_in,
                              void* d_out, int out_size) {
    const float* x     = (const float*)d_in[0];
    const int*   ei    = (const int*)  d_in[1];
    const float* ea    = (const float*)d_in[2];
    const float* W1    = (const float*)d_in[3];
    const float* root1 = (const float*)d_in[4];
    const float* b1    = (const float*)d_in[5];
    const float* W2    = (const float*)d_in[6];
    const float* root2 = (const float*)d_in[7];
    const float* b2    = (const float*)d_in[8];
    const float* m1w   = (const float*)d_in[9];
    const float* m1b   = (const float*)d_in[10];
    const float* m2w   = (const float*)d_in[11];
    const float* m2b   = (const float*)d_in[12];
    float* out = (float*)d_out;

    const int ZERO_BLOCKS = (N_NODES * D + 255) / 256;
    const int EDGE_BLOCKS = (int)(((long long)N_EDGES * 16 + 127) / 128);
    const int NODE_BLOCKS = (N_NODES + 7) / 8;

    // ---- Layer 1 (K=3, KE=9) ----
    zero_accum_kernel<<<ZERO_BLOCKS, 256>>>();
    {
        long long total = (long long)N_NODES * 9 * D;
        int blocks = (int)((total + 255) / 256);
        compute_Y_kernel<false><<<blocks, 256>>>(x, W1, 9);
    }
    edge_pass_kernel<3><<<EDGE_BLOCKS, 128>>>(ei, ea);
    node_pass_kernel<false><<<NODE_BLOCKS, 256>>>(x, root1, b1);

    // ---- Layer 2 (K=5, KE=25) ----
    zero_accum_kernel<<<ZERO_BLOCKS, 256>>>();
    {
        long long total = (long long)N_NODES * 25 * D;
        int blocks = (int)((total + 255) / 256);
        compute_Y_kernel<true><<<blocks, 256>>>(nullptr, W2, 25);
    }
    edge_pass_kernel<5><<<EDGE_BLOCKS, 128>>>(ei, ea);
    node_pass_kernel<true><<<NODE_BLOCKS, 256>>>(nullptr, root2, b2);

    // ---- MLP tail ----
    mlp_kernel<<<NODE_BLOCKS, 256>>>(m1w, m1b, m2w, m2b, out);
}

// round 2
// speedup vs baseline: 1.7468x; 1.7468x over previous
#include <cuda_runtime.h>
#include <math.h>

#define N_NODES 50000
#define N_EDGES 800000
#define D 64
#define C 8

#define SCAN_BLOCK 1024
#define SCAN_NBLK ((N_NODES + SCAN_BLOCK - 1) / SCAN_BLOCK)   // 49

typedef unsigned long long ull;

// ---------------- scratch (device globals; no allocations allowed) ----------
__device__ float g_Z[(size_t)N_NODES * 25 * D];   // basis-space accumulators (max KE=25)
__device__ float g_h[(size_t)N_NODES * D];        // node features between layers
__device__ int   g_cnt[N_NODES];
__device__ int   g_off[N_NODES + 1];
__device__ int   g_fill[N_NODES];
__device__ int   g_part[SCAN_NBLK];
__device__ int   g_order[N_EDGES];

// ---------------- f32x2 helpers ---------------------------------------------
__device__ __forceinline__ ull pack2(float x) {
    ull r;
    asm("mov.b64 %0, {%1, %1};" : "=l"(r) : "f"(x));
    return r;
}
__device__ __forceinline__ void fma2(ull &acc, ull a, ull b) {
    asm("fma.rn.f32x2 %0, %1, %2, %3;" : "=l"(acc) : "l"(a), "l"(b), "l"(acc));
}
__device__ __forceinline__ float2 unpack2(ull v) {
    float2 f;
    asm("mov.b64 {%0, %1}, %2;" : "=f"(f.x), "=f"(f.y) : "l"(v));
    return f;
}

// ---------------- CSR build --------------------------------------------------
__global__ void zero_int_kernel() {
    int i = blockIdx.x * blockDim.x + threadIdx.x;
    if (i < N_NODES) { g_cnt[i] = 0; g_fill[i] = 0; }
}

__global__ void hist_kernel(const int* __restrict__ ei) {
    int e = blockIdx.x * blockDim.x + threadIdx.x;
    if (e < N_EDGES) atomicAdd(&g_cnt[ei[N_EDGES + e]], 1);
}

__global__ void scan1_kernel() {
    __shared__ int sh[SCAN_BLOCK];
    int tid = threadIdx.x;
    int i = blockIdx.x * SCAN_BLOCK + tid;
    int v = (i < N_NODES) ? g_cnt[i] : 0;
    sh[tid] = v;
    __syncthreads();
#pragma unroll
    for (int o = 1; o < SCAN_BLOCK; o <<= 1) {
        int t = (tid >= o) ? sh[tid - o] : 0;
        __syncthreads();
        sh[tid] += t;
        __syncthreads();
    }
    if (i < N_NODES) g_off[i] = sh[tid] - v;           // block-local exclusive
    if (tid == SCAN_BLOCK - 1) g_part[blockIdx.x] = sh[tid];
}

__global__ void scan2_kernel() {
    if (threadIdx.x == 0) {
        int run = 0;
        for (int b = 0; b < SCAN_NBLK; b++) {
            int t = g_part[b];
            g_part[b] = run;
            run += t;
        }
    }
}

__global__ void scan3_kernel() {
    int i = blockIdx.x * SCAN_BLOCK + threadIdx.x;
    if (i < N_NODES) g_off[i] += g_part[blockIdx.x];
    if (i == 0) g_off[N_NODES] = N_EDGES;
}

__global__ void scatter_kernel(const int* __restrict__ ei) {
    int e = blockIdx.x * blockDim.x + threadIdx.x;
    if (e < N_EDGES) {
        int dst = ei[N_EDGES + e];
        int pos = g_off[dst] + atomicAdd(&g_fill[dst], 1);
        g_order[pos] = e;
    }
}

// ---------------- edge aggregation in basis space ----------------------------
// One block per dst node. Z[dst,k,:] = (1/max(cnt,1)) * sum_edges B_s(e) * x[src_e,:]
template<int K>
__global__ void aggregate_kernel(const float* __restrict__ hin,
                                 const int* __restrict__ ei,
                                 const float* __restrict__ ea) {
    const int KE = K * K;
    __shared__ float Zs[K * K * D];
    int n = blockIdx.x;
    int tid = threadIdx.x;          // 256
    int slot = tid >> 6;            // 4 concurrent edges
    int d = tid & 63;

    for (int i = tid; i < KE * D; i += 256) Zs[i] = 0.0f;
    __syncthreads();

    int e0 = g_off[n], e1 = g_off[n + 1];
    for (int t = e0 + slot; t < e1; t += 4) {
        int e = g_order[t];
        int src = ei[e];
        float p0 = ea[2 * e + 0];
        float p1 = ea[2 * e + 1];

        float v0 = p0 * (float)(K - 1);
        float lo0 = floorf(v0);
        float f0 = v0 - lo0;
        int l0 = (int)lo0;
        int i00 = min(max(l0, 0), K - 1);
        int i01 = min(max(l0 + 1, 0), K - 1);
        float v1 = p1 * (float)(K - 1);
        float lo1 = floorf(v1);
        float f1 = v1 - lo1;
        int l1 = (int)lo1;
        int i10 = min(max(l1, 0), K - 1);
        int i11 = min(max(l1 + 1, 0), K - 1);

        float b00 = 1.0f - f0, b01 = f0;
        float b10 = 1.0f - f1, b11 = f1;

        float xd = hin[(size_t)src * D + d];

        atomicAdd(&Zs[(i00 + i10 * K) * D + d], b00 * b10 * xd);
        atomicAdd(&Zs[(i00 + i11 * K) * D + d], b00 * b11 * xd);
        atomicAdd(&Zs[(i01 + i10 * K) * D + d], b01 * b10 * xd);
        atomicAdd(&Zs[(i01 + i11 * K) * D + d], b01 * b11 * xd);
    }
    __syncthreads();

    float invc = 1.0f / fmaxf((float)(e1 - e0), 1.0f);
    float* zout = g_Z + (size_t)n * KE * D;
    for (int i = tid; i < KE * D; i += 256) zout[i] = Zs[i] * invc;
}

// ---------------- fused GEMM: hout = ELU( sum_k Z[n,k]·W[k] + hin[n]·root + b )
// A = [Z slots 0..KE-1, hin as slot KE], B = [W[k], root]. f32x2 inner product.
#define BN 64
#define AS_STRIDE 68   // row pad: 16B aligned, spreads banks

template<int KE>
__global__ void gemm_kernel(const float* __restrict__ Z,
                            const float* __restrict__ hin,
                            const float* __restrict__ W,
                            const float* __restrict__ root,
                            const float* __restrict__ bias,
                            float* __restrict__ hout) {
    const int KS = KE + 1;
    extern __shared__ float sm[];
    float* As = sm;                           // [2][BN][AS_STRIDE]
    float* Bs = sm + 2 * BN * AS_STRIDE;      // [2][64][64]
    const int tid = threadIdx.x;              // 128
    const int n0 = blockIdx.x * BN;
    const int ng = tid >> 3;                  // 0..15 -> nodes 4*ng..4*ng+3
    const int o8 = tid & 7;                   // outputs o8*8..o8*8+7

    ull acc[16];
#pragma unroll
    for (int i = 0; i < 16; i++) acc[i] = 0ULL;

    // ---- prefetch stage for slot k into buffer 'stage'
    auto prefetch = [&](int k, int stage) {
#pragma unroll
        for (int i = 0; i < 8; i++) {
            int c = tid + i * 128;            // 1024 chunks of 16B
            int row = c >> 4, q = c & 15;
            int n = n0 + row;
            if (n > N_NODES - 1) n = N_NODES - 1;
            const float* src = (k < KE)
                ? (Z + ((size_t)n * KE + k) * D + q * 4)
                : (hin + (size_t)n * D + q * 4);
            unsigned sa = (unsigned)__cvta_generic_to_shared(
                As + (size_t)stage * BN * AS_STRIDE + row * AS_STRIDE + q * 4);
            asm volatile("cp.async.ca.shared.global [%0], [%1], 16;" :: "r"(sa), "l"(src));
        }
        const float* wsrc = (k < KE) ? (W + (size_t)k * D * D) : root;
#pragma unroll
        for (int i = 0; i < 8; i++) {
            int c = tid + i * 128;
            unsigned sa = (unsigned)__cvta_generic_to_shared(Bs + stage * 4096 + c * 4);
            asm volatile("cp.async.ca.shared.global [%0], [%1], 16;" :: "r"(sa), "l"(wsrc + c * 4));
        }
        asm volatile("cp.async.commit_group;");
    };

    prefetch(0, 0);
    int buf = 0;
    for (int k = 0; k < KS; k++) {
        if (k + 1 < KS) {
            prefetch(k + 1, buf ^ 1);
            asm volatile("cp.async.wait_group 1;");
        } else {
            asm volatile("cp.async.wait_group 0;");
        }
        __syncthreads();

        const float* a_base = As + (size_t)buf * BN * AS_STRIDE;
        const float* b_base = Bs + buf * 4096;
#pragma unroll 4
        for (int d4 = 0; d4 < 16; d4++) {
            float4 av[4];
#pragma unroll
            for (int ni = 0; ni < 4; ni++)
                av[ni] = *reinterpret_cast<const float4*>(
                    a_base + (4 * ng + ni) * AS_STRIDE + d4 * 4);
#pragma unroll
            for (int j = 0; j < 4; j++) {
                const float* brow = b_base + (d4 * 4 + j) * D + o8 * 8;
                ull w0 = *reinterpret_cast<const ull*>(brow + 0);
                ull w1 = *reinterpret_cast<const ull*>(brow + 2);
                ull w2 = *reinterpret_cast<const ull*>(brow + 4);
                ull w3 = *reinterpret_cast<const ull*>(brow + 6);
#pragma unroll
                for (int ni = 0; ni < 4; ni++) {
                    float a = (j == 0) ? av[ni].x : (j == 1) ? av[ni].y
                             : (j == 2) ? av[ni].z : av[ni].w;
                    ull ap = pack2(a);
                    fma2(acc[ni * 4 + 0], ap, w0);
                    fma2(acc[ni * 4 + 1], ap, w1);
                    fma2(acc[ni * 4 + 2], ap, w2);
                    fma2(acc[ni * 4 + 3], ap, w3);
                }
            }
        }
        __syncthreads();
        buf ^= 1;
    }

    // epilogue: + bias, ELU, store (2x STG.128 per node)
    float b[8];
#pragma unroll
    for (int j = 0; j < 8; j++) b[j] = bias[o8 * 8 + j];
#pragma unroll
    for (int ni = 0; ni < 4; ni++) {
        int n = n0 + 4 * ng + ni;
        if (n >= N_NODES) continue;
        float r[8];
#pragma unroll
        for (int p = 0; p < 4; p++) {
            float2 v = unpack2(acc[ni * 4 + p]);
            r[2 * p] = v.x;
            r[2 * p + 1] = v.y;
        }
#pragma unroll
        for (int j = 0; j < 8; j++) {
            float t = r[j] + b[j];
            r[j] = (t > 0.0f) ? t : expm1f(t);
        }
        float4 s0 = make_float4(r[0], r[1], r[2], r[3]);
        float4 s1 = make_float4(r[4], r[5], r[6], r[7]);
        *reinterpret_cast<float4*>(hout + (size_t)n * D + o8 * 8) = s0;
        *reinterpret_cast<float4*>(hout + (size_t)n * D + o8 * 8 + 4) = s1;
    }
}

// ---------------- MLP tail ---------------------------------------------------
__global__ void mlp_kernel(const float* __restrict__ w1, const float* __restrict__ b1,
                           const float* __restrict__ w2, const float* __restrict__ b2,
                           float* __restrict__ out) {
    __shared__ float t1s[8][D];
    int wid = threadIdx.x >> 5;
    int lane = threadIdx.x & 31;
    int n = blockIdx.x * 8 + wid;
    if (n >= N_NODES) return;

    const float* hr = g_h + (size_t)n * D;
    float a0 = 0.0f, a1 = 0.0f;
#pragma unroll
    for (int d = 0; d < D; d++) {
        float hv = hr[d];
        a0 = fmaf(hv, w1[d * D + lane], a0);
        a1 = fmaf(hv, w1[d * D + lane + 32], a1);
    }
    a0 += b1[lane];
    a1 += b1[lane + 32];
    t1s[wid][lane] = fmaxf(a0, 0.0f);
    t1s[wid][lane + 32] = fmaxf(a1, 0.0f);
    __syncwarp();

    if (lane < C) {
        float acc = b2[lane];
#pragma unroll
        for (int d = 0; d < D; d++)
            acc = fmaf(t1s[wid][d], w2[d * C + lane], acc);
        out[(size_t)n * C + lane] = fmaxf(acc, 0.0f);
    }
}

// ---------------- launch -----------------------------------------------------
extern "C" void kernel_launch(void* const* d_in, const int* in_sizes, int n_in,
                              void* d_out, int out_size) {
    const float* x     = (const float*)d_in[0];
    const int*   ei    = (const int*)  d_in[1];
    const float* ea    = (const float*)d_in[2];
    const float* W1    = (const float*)d_in[3];
    const float* root1 = (const float*)d_in[4];
    const float* b1    = (const float*)d_in[5];
    const float* W2    = (const float*)d_in[6];
    const float* root2 = (const float*)d_in[7];
    const float* b2    = (const float*)d_in[8];
    const float* m1w   = (const float*)d_in[9];
    const float* m1b   = (const float*)d_in[10];
    const float* m2w   = (const float*)d_in[11];
    const float* m2b   = (const float*)d_in[12];
    float* out = (float*)d_out;

    const int SMEM_GEMM = (2 * BN * AS_STRIDE + 2 * 64 * 64) * sizeof(float); // 67584
    cudaFuncSetAttribute(gemm_kernel<9>,  cudaFuncAttributeMaxDynamicSharedMemorySize, SMEM_GEMM);
    cudaFuncSetAttribute(gemm_kernel<25>, cudaFuncAttributeMaxDynamicSharedMemorySize, SMEM_GEMM);

    float* gZ;   cudaGetSymbolAddress((void**)&gZ, g_Z);
    float* gh;   cudaGetSymbolAddress((void**)&gh, g_h);

    const int GEMM_BLOCKS = (N_NODES + BN - 1) / BN;     // 782
    const int EB = (N_EDGES + 255) / 256;

    // ---- CSR build (shared by both layers) ----
    zero_int_kernel<<<(N_NODES + 255) / 256, 256>>>();
    hist_kernel<<<EB, 256>>>(ei);
    scan1_kernel<<<SCAN_NBLK, SCAN_BLOCK>>>();
    scan2_kernel<<<1, 32>>>();
    scan3_kernel<<<SCAN_NBLK, SCAN_BLOCK>>>();
    scatter_kernel<<<EB, 256>>>(ei);

    // ---- Layer 1 (K=3) ----
    aggregate_kernel<3><<<N_NODES, 256>>>(x, ei, ea);
    gemm_kernel<9><<<GEMM_BLOCKS, 128, SMEM_GEMM>>>(gZ, x, W1, root1, b1, gh);

    // ---- Layer 2 (K=5) ----
    aggregate_kernel<5><<<N_NODES, 256>>>(gh, ei, ea);
    gemm_kernel<25><<<GEMM_BLOCKS, 128, SMEM_GEMM>>>(gZ, gh, W2, root2, b2, gh);

    // ---- MLP tail ----
    mlp_kernel<<<(N_NODES + 7) / 8, 256>>>(m1w, m1b, m2w, m2b, out);
}

// round 3
// speedup vs baseline: 2.1161x; 1.2114x over previous
#include <cuda_runtime.h>
#include <math.h>

#define N_NODES 50000
#define N_EDGES 800000
#define D 64
#define C 8

typedef unsigned long long ull;

// ---------------- scratch (device globals; no allocations allowed) ----------
__device__ float g_Z[(size_t)N_NODES * 25 * D];   // basis-space accumulators (max KE=25)
__device__ float g_h[(size_t)N_NODES * D];        // node features between layers
__device__ int   g_cnt[N_NODES];
__device__ int   g_off[N_NODES + 1];
__device__ int   g_fill[N_NODES];
__device__ int   g_order[N_EDGES];

// ---------------- f32x2 helpers ---------------------------------------------
__device__ __forceinline__ ull pack2(float x) {
    ull r;
    asm("mov.b64 %0, {%1, %1};" : "=l"(r) : "f"(x));
    return r;
}
__device__ __forceinline__ void fma2(ull &acc, ull a, ull b) {
    asm("fma.rn.f32x2 %0, %1, %2, %3;" : "=l"(acc) : "l"(a), "l"(b), "l"(acc));
}
__device__ __forceinline__ float2 unpack2(ull v) {
    float2 f;
    asm("mov.b64 {%0, %1}, %2;" : "=f"(f.x), "=f"(f.y) : "l"(v));
    return f;
}

// ---------------- CSR build --------------------------------------------------
__global__ void zero_int_kernel() {
    int i = blockIdx.x * blockDim.x + threadIdx.x;
    if (i < N_NODES) { g_cnt[i] = 0; g_fill[i] = 0; }
}

__global__ void hist_kernel(const int* __restrict__ ei) {
    int e = blockIdx.x * blockDim.x + threadIdx.x;
    if (e < N_EDGES) atomicAdd(&g_cnt[ei[N_EDGES + e]], 1);
}

// Single-block exclusive scan of g_cnt -> g_off. 1024 threads, 49 items each.
__global__ void scan_kernel() {
    __shared__ int sums[1024];
    const int CH = (N_NODES + 1023) / 1024;   // 49
    int tid = threadIdx.x;
    int base = tid * CH;
    int s = 0;
#pragma unroll 7
    for (int i = 0; i < CH; i++) {
        int idx = base + i;
        if (idx < N_NODES) s += g_cnt[idx];
    }
    sums[tid] = s;
    __syncthreads();
#pragma unroll
    for (int o = 1; o < 1024; o <<= 1) {
        int t = (tid >= o) ? sums[tid - o] : 0;
        __syncthreads();
        sums[tid] += t;
        __syncthreads();
    }
    int run = (tid > 0) ? sums[tid - 1] : 0;
    for (int i = 0; i < CH; i++) {
        int idx = base + i;
        if (idx < N_NODES) {
            int c = g_cnt[idx];
            g_off[idx] = run;
            run += c;
        }
    }
    if (tid == 1023) g_off[N_NODES] = N_EDGES;
}

__global__ void scatter_kernel(const int* __restrict__ ei) {
    int e = blockIdx.x * blockDim.x + threadIdx.x;
    if (e < N_EDGES) {
        int dst = ei[N_EDGES + e];
        int pos = g_off[dst] + atomicAdd(&g_fill[dst], 1);
        g_order[pos] = e;
    }
}

// ---------------- edge aggregation in basis space ----------------------------
// One warp per dst node, 8 nodes per block. Each thread owns two feature dims
// (lane, lane+32) with EXCLUSIVE smem accumulator columns (stride KE is odd ->
// bank-conflict-free). Per 32-edge chunk: lanes cooperatively fetch edge
// metadata (src, packed spline indices, basis weights) in parallel, then the
// accumulate loop only touches x[src] in global (hoistable) + smem.
template<int K>
__global__ void aggregate_kernel(const float* __restrict__ hin,
                                 const int* __restrict__ ei,
                                 const float* __restrict__ ea) {
    const int KE = K * K;
    __shared__ float  Zs[8][64][K * K];
    __shared__ int    m_src[8][32];
    __shared__ unsigned m_wi[8][32];
    __shared__ float4 m_B[8][32];

    int g = threadIdx.x >> 5;
    int lane = threadIdx.x & 31;
    int n = blockIdx.x * 8 + g;
    bool active = n < N_NODES;

    float* z0 = &Zs[g][lane][0];
    float* z1 = &Zs[g][lane + 32][0];
#pragma unroll
    for (int k = 0; k < KE; k++) { z0[k] = 0.0f; z1[k] = 0.0f; }

    int e0 = 0, e1 = 0;
    if (active) { e0 = g_off[n]; e1 = g_off[n + 1]; }

    for (int c = e0; c < e1; c += 32) {
        int cnt = min(32, e1 - c);
        if (lane < cnt) {
            int e = g_order[c + lane];
            int src = ei[e];
            float p0 = ea[2 * e + 0];
            float p1 = ea[2 * e + 1];

            float v0 = p0 * (float)(K - 1);
            float lo0 = floorf(v0);
            float f0 = v0 - lo0;
            int l0 = (int)lo0;
            int i00 = min(max(l0, 0), K - 1);
            int i01 = min(max(l0 + 1, 0), K - 1);
            float v1 = p1 * (float)(K - 1);
            float lo1 = floorf(v1);
            float f1 = v1 - lo1;
            int l1 = (int)lo1;
            int i10 = min(max(l1, 0), K - 1);
            int i11 = min(max(l1 + 1, 0), K - 1);

            float b00 = 1.0f - f0, b01 = f0;
            float b10 = 1.0f - f1, b11 = f1;

            m_src[g][lane] = src;
            m_wi[g][lane] = (unsigned)(i00 + i10 * K)
                          | ((unsigned)(i00 + i11 * K) << 8)
                          | ((unsigned)(i01 + i10 * K) << 16)
                          | ((unsigned)(i01 + i11 * K) << 24);
            m_B[g][lane] = make_float4(b00 * b10, b00 * b11, b01 * b10, b01 * b11);
        }
        __syncwarp();

#pragma unroll 4
        for (int j = 0; j < cnt; j++) {
            int src = m_src[g][j];
            unsigned wi = m_wi[g][j];
            float4 B = m_B[g][j];
            float x0 = hin[(size_t)src * D + lane];
            float x1 = hin[(size_t)src * D + lane + 32];
            int k0 = wi & 255, k1 = (wi >> 8) & 255;
            int k2 = (wi >> 16) & 255, k3 = wi >> 24;
            z0[k0] += B.x * x0;  z0[k1] += B.y * x0;
            z0[k2] += B.z * x0;  z0[k3] += B.w * x0;
            z1[k0] += B.x * x1;  z1[k1] += B.y * x1;
            z1[k2] += B.z * x1;  z1[k3] += B.w * x1;
        }
        __syncwarp();
    }

    if (active) {
        float invc = 1.0f / fmaxf((float)(e1 - e0), 1.0f);
        float* zout = g_Z + (size_t)n * KE * D;
#pragma unroll
        for (int k = 0; k < KE; k++) {
            zout[k * D + lane]      = z0[k] * invc;
            zout[k * D + lane + 32] = z1[k] * invc;
        }
    }
}

// ---------------- fused GEMM: hout = ELU( sum_k Z[n,k]·W[k] + hin[n]·root + b )
// A = [Z slots 0..KE-1, hin as slot KE], B = [W[k], root]. f32x2 inner product.
#define BN 64
#define AS_STRIDE 68   // row pad: 16B aligned, spreads banks

template<int KE>
__global__ void gemm_kernel(const float* __restrict__ Z,
                            const float* __restrict__ hin,
                            const float* __restrict__ W,
                            const float* __restrict__ root,
                            const float* __restrict__ bias,
                            float* __restrict__ hout) {
    const int KS = KE + 1;
    extern __shared__ float sm[];
    float* As = sm;                           // [2][BN][AS_STRIDE]
    float* Bs = sm + 2 * BN * AS_STRIDE;      // [2][64][64]
    const int tid = threadIdx.x;              // 128
    const int n0 = blockIdx.x * BN;
    const int ng = tid >> 3;                  // 0..15 -> nodes 4*ng..4*ng+3
    const int o8 = tid & 7;                   // outputs o8*8..o8*8+7

    ull acc[16];
#pragma unroll
    for (int i = 0; i < 16; i++) acc[i] = 0ULL;

    auto prefetch = [&](int k, int stage) {
#pragma unroll
        for (int i = 0; i < 8; i++) {
            int c = tid + i * 128;            // 1024 chunks of 16B
            int row = c >> 4, q = c & 15;
            int n = n0 + row;
            if (n > N_NODES - 1) n = N_NODES - 1;
            const float* src = (k < KE)
                ? (Z + ((size_t)n * KE + k) * D + q * 4)
                : (hin + (size_t)n * D + q * 4);
            unsigned sa = (unsigned)__cvta_generic_to_shared(
                As + (size_t)stage * BN * AS_STRIDE + row * AS_STRIDE + q * 4);
            asm volatile("cp.async.ca.shared.global [%0], [%1], 16;" :: "r"(sa), "l"(src));
        }
        const float* wsrc = (k < KE) ? (W + (size_t)k * D * D) : root;
#pragma unroll
        for (int i = 0; i < 8; i++) {
            int c = tid + i * 128;
            unsigned sa = (unsigned)__cvta_generic_to_shared(Bs + stage * 4096 + c * 4);
            asm volatile("cp.async.ca.shared.global [%0], [%1], 16;" :: "r"(sa), "l"(wsrc + c * 4));
        }
        asm volatile("cp.async.commit_group;");
    };

    prefetch(0, 0);
    int buf = 0;
    for (int k = 0; k < KS; k++) {
        if (k + 1 < KS) {
            prefetch(k + 1, buf ^ 1);
            asm volatile("cp.async.wait_group 1;");
        } else {
            asm volatile("cp.async.wait_group 0;");
        }
        __syncthreads();

        const float* a_base = As + (size_t)buf * BN * AS_STRIDE;
        const float* b_base = Bs + buf * 4096;
#pragma unroll 4
        for (int d4 = 0; d4 < 16; d4++) {
            float4 av[4];
#pragma unroll
            for (int ni = 0; ni < 4; ni++)
                av[ni] = *reinterpret_cast<const float4*>(
                    a_base + (4 * ng + ni) * AS_STRIDE + d4 * 4);
#pragma unroll
            for (int j = 0; j < 4; j++) {
                const float* brow = b_base + (d4 * 4 + j) * D + o8 * 8;
                ull w0 = *reinterpret_cast<const ull*>(brow + 0);
                ull w1 = *reinterpret_cast<const ull*>(brow + 2);
                ull w2 = *reinterpret_cast<const ull*>(brow + 4);
                ull w3 = *reinterpret_cast<const ull*>(brow + 6);
#pragma unroll
                for (int ni = 0; ni < 4; ni++) {
                    float a = (j == 0) ? av[ni].x : (j == 1) ? av[ni].y
                             : (j == 2) ? av[ni].z : av[ni].w;
                    ull ap = pack2(a);
                    fma2(acc[ni * 4 + 0], ap, w0);
                    fma2(acc[ni * 4 + 1], ap, w1);
                    fma2(acc[ni * 4 + 2], ap, w2);
                    fma2(acc[ni * 4 + 3], ap, w3);
                }
            }
        }
        __syncthreads();
        buf ^= 1;
    }

    // epilogue: + bias, ELU, store
    float b[8];
#pragma unroll
    for (int j = 0; j < 8; j++) b[j] = bias[o8 * 8 + j];
#pragma unroll
    for (int ni = 0; ni < 4; ni++) {
        int n = n0 + 4 * ng + ni;
        if (n >= N_NODES) continue;
        float r[8];
#pragma unroll
        for (int p = 0; p < 4; p++) {
            float2 v = unpack2(acc[ni * 4 + p]);
            r[2 * p] = v.x;
            r[2 * p + 1] = v.y;
        }
#pragma unroll
        for (int j = 0; j < 8; j++) {
            float t = r[j] + b[j];
            r[j] = (t > 0.0f) ? t : expm1f(t);
        }
        float4 s0 = make_float4(r[0], r[1], r[2], r[3]);
        float4 s1 = make_float4(r[4], r[5], r[6], r[7]);
        *reinterpret_cast<float4*>(hout + (size_t)n * D + o8 * 8) = s0;
        *reinterpret_cast<float4*>(hout + (size_t)n * D + o8 * 8 + 4) = s1;
    }
}

// ---------------- MLP tail ---------------------------------------------------
__global__ void mlp_kernel(const float* __restrict__ w1, const float* __restrict__ b1,
                           const float* __restrict__ w2, const float* __restrict__ b2,
                           float* __restrict__ out) {
    __shared__ float t1s[8][D];
    int wid = threadIdx.x >> 5;
    int lane = threadIdx.x & 31;
    int n = blockIdx.x * 8 + wid;
    if (n >= N_NODES) return;

    const float* hr = g_h + (size_t)n * D;
    float a0 = 0.0f, a1 = 0.0f;
#pragma unroll
    for (int d = 0; d < D; d++) {
        float hv = hr[d];
        a0 = fmaf(hv, w1[d * D + lane], a0);
        a1 = fmaf(hv, w1[d * D + lane + 32], a1);
    }
    a0 += b1[lane];
    a1 += b1[lane + 32];
    t1s[wid][lane] = fmaxf(a0, 0.0f);
    t1s[wid][lane + 32] = fmaxf(a1, 0.0f);
    __syncwarp();

    if (lane < C) {
        float acc = b2[lane];
#pragma unroll
        for (int d = 0; d < D; d++)
            acc = fmaf(t1s[wid][d], w2[d * C + lane], acc);
        out[(size_t)n * C + lane] = fmaxf(acc, 0.0f);
    }
}

// ---------------- launch -----------------------------------------------------
extern "C" void kernel_launch(void* const* d_in, const int* in_sizes, int n_in,
                              void* d_out, int out_size) {
    const float* x     = (const float*)d_in[0];
    const int*   ei    = (const int*)  d_in[1];
    const float* ea    = (const float*)d_in[2];
    const float* W1    = (const float*)d_in[3];
    const float* root1 = (const float*)d_in[4];
    const float* b1    = (const float*)d_in[5];
    const float* W2    = (const float*)d_in[6];
    const float* root2 = (const float*)d_in[7];
    const float* b2    = (const float*)d_in[8];
    const float* m1w   = (const float*)d_in[9];
    const float* m1b   = (const float*)d_in[10];
    const float* m2w   = (const float*)d_in[11];
    const float* m2b   = (const float*)d_in[12];
    float* out = (float*)d_out;

    const int SMEM_GEMM = (2 * BN * AS_STRIDE + 2 * 64 * 64) * sizeof(float); // 67584
    cudaFuncSetAttribute(gemm_kernel<9>,  cudaFuncAttributeMaxDynamicSharedMemorySize, SMEM_GEMM);
    cudaFuncSetAttribute(gemm_kernel<25>, cudaFuncAttributeMaxDynamicSharedMemorySize, SMEM_GEMM);

    float* gZ;   cudaGetSymbolAddress((void**)&gZ, g_Z);
    float* gh;   cudaGetSymbolAddress((void**)&gh, g_h);

    const int GEMM_BLOCKS = (N_NODES + BN - 1) / BN;     // 782
    const int AGG_BLOCKS  = (N_NODES + 7) / 8;           // 6250
    const int EB = (N_EDGES + 255) / 256;

    // ---- CSR build (shared by both layers) ----
    zero_int_kernel<<<(N_NODES + 255) / 256, 256>>>();
    hist_kernel<<<EB, 256>>>(ei);
    scan_kernel<<<1, 1024>>>();
    scatter_kernel<<<EB, 256>>>(ei);

    // ---- Layer 1 (K=3) ----
    aggregate_kernel<3><<<AGG_BLOCKS, 256>>>(x, ei, ea);
    gemm_kernel<9><<<GEMM_BLOCKS, 128, SMEM_GEMM>>>(gZ, x, W1, root1, b1, gh);

    // ---- Layer 2 (K=5) ----
    aggregate_kernel<5><<<AGG_BLOCKS, 256>>>(gh, ei, ea);
    gemm_kernel<25><<<GEMM_BLOCKS, 128, SMEM_GEMM>>>(gZ, gh, W2, root2, b2, gh);

    // ---- MLP tail ----
    mlp_kernel<<<(N_NODES + 7) / 8, 256>>>(m1w, m1b, m2w, m2b, out);
}